// round 10
// baseline (speedup 1.0000x reference)
#include <cuda_runtime.h>

#define NQ 10000
#define BB 128
#define SS 200
#define DKk 128
#define DVv 64
#define ROWS (BB*SS)     // 25600

typedef unsigned long long u64;

__device__ __forceinline__ u64 pk2(float lo, float hi) {
    u64 r; asm("mov.b64 %0,{%1,%2};" : "=l"(r) : "f"(lo), "f"(hi)); return r;
}
__device__ __forceinline__ float2 up2(u64 a) {
    float2 v; asm("mov.b64 {%0,%1},%2;" : "=f"(v.x), "=f"(v.y) : "l"(a)); return v;
}
__device__ __forceinline__ u64 fma2(u64 a, u64 b, u64 c) {
    u64 d; asm("fma.rn.f32x2 %0,%1,%2,%3;" : "=l"(d) : "l"(a), "l"(b), "l"(c)); return d;
}
__device__ __forceinline__ u64 add2(u64 a, u64 b) {
    u64 d; asm("add.rn.f32x2 %0,%1,%2;" : "=l"(d) : "l"(a), "l"(b)); return d;
}
__device__ __forceinline__ float tanha(float x) {
    float y; asm("tanh.approx.f32 %0,%1;" : "=f"(y) : "f"(x)); return y;
}

// Scratch
__device__ float g_w[ROWS*DVv];
__device__ float g_e[ROWS*DKk];
__device__ float g_a[ROWS*DKk];
__device__ float g_reads[ROWS*DKk];

// ---------------------------------------------------------------------------
// Kernel 1: w = softmax(k_emb[q] @ Mk^T). 256-row tiles, grid 100 (ONE wave).
// (unchanged from R9 — register headroom too tight to pipeline safely)
// ---------------------------------------------------------------------------
__global__ __launch_bounds__(512, 1)
void kern_w(const int* __restrict__ qseq,
            const float* __restrict__ k_emb,
            const float* __restrict__ Mk) {
    extern __shared__ float sm[];
    float* shAT = sm;               // [128][264]
    float* shBt = sm + 128 * 264;   // [128][68]
    __shared__ int shq[256];

    const int tid = threadIdx.x;
    const int lane = tid & 31;
    const int wid  = tid >> 5;

#pragma unroll
    for (int i = 0; i < 4; i++) {
        int idx = tid + i * 512;            // 0..2047 = 64 cols x 32 kc4
        int col = idx & 63, kc4 = idx >> 6;
        float4 v = *(const float4*)(Mk + col * DKk + kc4 * 4);
        shBt[(kc4 * 4 + 0) * 68 + col] = v.x;
        shBt[(kc4 * 4 + 1) * 68 + col] = v.y;
        shBt[(kc4 * 4 + 2) * 68 + col] = v.z;
        shBt[(kc4 * 4 + 3) * 68 + col] = v.w;
    }

    const int rowb = wid * 16;
    const int c0   = lane * 2;

    for (int t = blockIdx.x; t < ROWS / 256; t += gridDim.x) {
        __syncthreads();
        if (tid < 256) shq[tid] = qseq[t * 256 + tid];
        __syncthreads();
#pragma unroll
        for (int i = 0; i < 16; i++) {
            int idx = tid + i * 512;        // 0..8191 = 256 rows x 32 kc4
            int r = idx & 255, kc4 = idx >> 8;
            float4 v = *(const float4*)(k_emb + (size_t)shq[r] * DKk + kc4 * 4);
            shAT[(kc4 * 4 + 0) * 264 + r] = v.x;
            shAT[(kc4 * 4 + 1) * 264 + r] = v.y;
            shAT[(kc4 * 4 + 2) * 264 + r] = v.z;
            shAT[(kc4 * 4 + 3) * 264 + r] = v.w;
        }
        __syncthreads();

        u64 acc[8][2] = {};
#pragma unroll 4
        for (int kk = 0; kk < DKk; kk++) {
            const float* ab = shAT + kk * 264 + rowb;
            ulonglong2 a01 = *(const ulonglong2*)(ab);
            ulonglong2 a23 = *(const ulonglong2*)(ab + 4);
            ulonglong2 a45 = *(const ulonglong2*)(ab + 8);
            ulonglong2 a67 = *(const ulonglong2*)(ab + 12);
            float2 bf = *(const float2*)(shBt + kk * 68 + c0);
            u64 b0 = pk2(bf.x, bf.x), b1 = pk2(bf.y, bf.y);
            acc[0][0] = fma2(a01.x, b0, acc[0][0]);
            acc[0][1] = fma2(a01.x, b1, acc[0][1]);
            acc[1][0] = fma2(a01.y, b0, acc[1][0]);
            acc[1][1] = fma2(a01.y, b1, acc[1][1]);
            acc[2][0] = fma2(a23.x, b0, acc[2][0]);
            acc[2][1] = fma2(a23.x, b1, acc[2][1]);
            acc[3][0] = fma2(a23.y, b0, acc[3][0]);
            acc[3][1] = fma2(a23.y, b1, acc[3][1]);
            acc[4][0] = fma2(a45.x, b0, acc[4][0]);
            acc[4][1] = fma2(a45.x, b1, acc[4][1]);
            acc[5][0] = fma2(a45.y, b0, acc[5][0]);
            acc[5][1] = fma2(a45.y, b1, acc[5][1]);
            acc[6][0] = fma2(a67.x, b0, acc[6][0]);
            acc[6][1] = fma2(a67.x, b1, acc[6][1]);
            acc[7][0] = fma2(a67.y, b0, acc[7][0]);
            acc[7][1] = fma2(a67.y, b1, acc[7][1]);
        }
#pragma unroll
        for (int rp = 0; rp < 8; rp++) {
            float2 v0 = up2(acc[rp][0]), v1 = up2(acc[rp][1]);
            float mlo = fmaxf(v0.x, v1.x);
            float mhi = fmaxf(v0.y, v1.y);
#pragma unroll
            for (int o = 1; o < 32; o <<= 1) {
                mlo = fmaxf(mlo, __shfl_xor_sync(0xffffffffu, mlo, o));
                mhi = fmaxf(mhi, __shfl_xor_sync(0xffffffffu, mhi, o));
            }
            float l0 = __expf(v0.x - mlo), l1 = __expf(v1.x - mlo);
            float h0 = __expf(v0.y - mhi), h1 = __expf(v1.y - mhi);
            float slo = l0 + l1, shi = h0 + h1;
#pragma unroll
            for (int o = 1; o < 32; o <<= 1) {
                slo += __shfl_xor_sync(0xffffffffu, slo, o);
                shi += __shfl_xor_sync(0xffffffffu, shi, o);
            }
            float ilo = 1.0f / slo, ihi = 1.0f / shi;
            int row = t * 256 + rowb + 2 * rp;
            *(float2*)(g_w + (size_t)row * DVv + c0) = make_float2(l0 * ilo, l1 * ilo);
            *(float2*)(g_w + (size_t)(row + 1) * DVv + c0) = make_float2(h0 * ihi, h1 * ihi);
        }
    }
}

// ---------------------------------------------------------------------------
// Kernel 2: e/a fused, matrix-split warps, SOFTWARE-PIPELINED inner loop.
// ---------------------------------------------------------------------------
__global__ __launch_bounds__(512, 1)
void kern_ea(const int* __restrict__ qseq, const int* __restrict__ cseq,
             const float* __restrict__ v_emb,
             const float* __restrict__ eW, const float* __restrict__ eb,
             const float* __restrict__ aW, const float* __restrict__ ab) {
    extern __shared__ float sm[];
    float* shAT = sm;                    // [128][68]
    float* shE  = sm + 128 * 68;         // [128][128]
    float* shAw = shE + 128 * 128;       // [128][128]
    float* shEb = shAw + 128 * 128;      // [128]
    float* shAb = shEb + 128;            // [128]
    __shared__ int shx[64];

    const int tid = threadIdx.x;
    const int lane = tid & 31;
    const int wid  = tid >> 5;

#pragma unroll
    for (int i = 0; i < 8; i++) {
        int idx = tid + i * 512;
        *(float4*)(shE  + idx * 4) = *(const float4*)(eW + idx * 4);
        *(float4*)(shAw + idx * 4) = *(const float4*)(aW + idx * 4);
    }
    if (tid < 128) { shEb[tid] = eb[tid]; shAb[tid] = ab[tid]; }

    const int mat  = wid >> 3;           // 0 = e, 1 = a
    const int rowb = (wid & 7) * 8;
    const int c0   = lane * 4;
    const float* W = mat ? shAw : shE;

    for (int t = blockIdx.x; t < ROWS / 64; t += gridDim.x) {
        __syncthreads();
        if (tid < 64) {
            int row = t * 64 + tid;
            shx[tid] = qseq[row] + NQ * cseq[row];
        }
        __syncthreads();
#pragma unroll
        for (int i = 0; i < 4; i++) {
            int idx = tid + i * 512;        // 0..2047 = 64 rows x 32 kc4
            int r = idx & 63, kc4 = idx >> 6;
            float4 v = *(const float4*)(v_emb + (size_t)shx[r] * DKk + kc4 * 4);
            shAT[(kc4 * 4 + 0) * 68 + r] = v.x;
            shAT[(kc4 * 4 + 1) * 68 + r] = v.y;
            shAT[(kc4 * 4 + 2) * 68 + r] = v.z;
            shAT[(kc4 * 4 + 3) * 68 + r] = v.w;
        }
        __syncthreads();

        // pipelined mainloop
        ulonglong2 cA = *(const ulonglong2*)(shAT + rowb);
        ulonglong2 cB = *(const ulonglong2*)(shAT + rowb + 4);
        float4 cbf = *(const float4*)(W + c0);
        u64 acc[4][4] = {};
#pragma unroll 4
        for (int kk = 0; kk < DKk; kk++) {
            int kn = (kk + 1 < DKk) ? kk + 1 : 0;
            const float* abn = shAT + kn * 68 + rowb;
            ulonglong2 nA = *(const ulonglong2*)(abn);
            ulonglong2 nB = *(const ulonglong2*)(abn + 4);
            float4 nbf = *(const float4*)(W + (kn << 7) + c0);
            u64 b0 = pk2(cbf.x, cbf.x), b1 = pk2(cbf.y, cbf.y);
            u64 b2 = pk2(cbf.z, cbf.z), b3 = pk2(cbf.w, cbf.w);
            acc[0][0] = fma2(cA.x, b0, acc[0][0]);
            acc[0][1] = fma2(cA.x, b1, acc[0][1]);
            acc[0][2] = fma2(cA.x, b2, acc[0][2]);
            acc[0][3] = fma2(cA.x, b3, acc[0][3]);
            acc[1][0] = fma2(cA.y, b0, acc[1][0]);
            acc[1][1] = fma2(cA.y, b1, acc[1][1]);
            acc[1][2] = fma2(cA.y, b2, acc[1][2]);
            acc[1][3] = fma2(cA.y, b3, acc[1][3]);
            acc[2][0] = fma2(cB.x, b0, acc[2][0]);
            acc[2][1] = fma2(cB.x, b1, acc[2][1]);
            acc[2][2] = fma2(cB.x, b2, acc[2][2]);
            acc[2][3] = fma2(cB.x, b3, acc[2][3]);
            acc[3][0] = fma2(cB.y, b0, acc[3][0]);
            acc[3][1] = fma2(cB.y, b1, acc[3][1]);
            acc[3][2] = fma2(cB.y, b2, acc[3][2]);
            acc[3][3] = fma2(cB.y, b3, acc[3][3]);
            cA = nA; cB = nB; cbf = nbf;
        }
        const float* bias = mat ? shAb : shEb;
        float b0 = bias[c0], b1 = bias[c0+1], b2 = bias[c0+2], b3 = bias[c0+3];
        float* outbuf = mat ? g_a : g_e;
#pragma unroll
        for (int rp = 0; rp < 4; rp++) {
            float2 v0 = up2(acc[rp][0]), v1 = up2(acc[rp][1]);
            float2 v2 = up2(acc[rp][2]), v3 = up2(acc[rp][3]);
            int row = t * 64 + rowb + 2 * rp;
            float4 olo, ohi;
            if (mat) {
                olo = make_float4(tanha(v0.x+b0), tanha(v1.x+b1), tanha(v2.x+b2), tanha(v3.x+b3));
                ohi = make_float4(tanha(v0.y+b0), tanha(v1.y+b1), tanha(v2.y+b2), tanha(v3.y+b3));
            } else {
                olo = make_float4(1.0f/(1.0f+__expf(-(v0.x+b0))), 1.0f/(1.0f+__expf(-(v1.x+b1))),
                                  1.0f/(1.0f+__expf(-(v2.x+b2))), 1.0f/(1.0f+__expf(-(v3.x+b3))));
                ohi = make_float4(1.0f/(1.0f+__expf(-(v0.y+b0))), 1.0f/(1.0f+__expf(-(v1.y+b1))),
                                  1.0f/(1.0f+__expf(-(v2.y+b2))), 1.0f/(1.0f+__expf(-(v3.y+b3))));
            }
            *(float4*)(outbuf + (size_t)row * DKk + c0) = olo;
            *(float4*)(outbuf + (size_t)(row + 1) * DKk + c0) = ohi;
        }
    }
}

// ---------------------------------------------------------------------------
// Kernel 3: sequential scan, 512 threads, v split 4-ways per column.
// j = wid*8 + (lane&7); vs = lane>>3 owns v in [vs*16, vs*16+16).
// Read combined via shfl_xor(8) + shfl_xor(16). Barrier-free, prefetched.
// ---------------------------------------------------------------------------
__global__ __launch_bounds__(512, 1)
void kern_scan(const float* __restrict__ Mv0) {
    const int b = blockIdx.x;
    const int tid = threadIdx.x;
    const int lane = tid & 31;
    const int wid  = tid >> 5;
    const int j  = wid * 8 + (lane & 7);
    const int vs = lane >> 3;        // 0..3
    const int vb = vs * 16;

    u64 M[8];
#pragma unroll
    for (int p = 0; p < 8; p++)
        M[p] = pk2(Mv0[(vb + 2*p) * DKk + j], Mv0[(vb + 2*p + 1) * DKk + j]);

    const float* wp = g_w + (size_t)b * SS * DVv + vb;
    const float* ep = g_e + (size_t)b * SS * DKk + j;
    const float* ap = g_a + (size_t)b * SS * DKk + j;
    float* rp = g_reads + (size_t)b * SS * DKk + j;

    u64 wc[8];
#pragma unroll
    for (int q = 0; q < 4; q++) {
        ulonglong2 tld = *(const ulonglong2*)(wp + q * 4);
        wc[2*q] = tld.x; wc[2*q+1] = tld.y;
    }
    float ec = ep[0], ac = ap[0];

#pragma unroll 2
    for (int s = 0; s < SS; s++) {
        int sn = (s + 1 < SS) ? s + 1 : s;
        u64 wn[8];
#pragma unroll
        for (int q = 0; q < 4; q++) {
            ulonglong2 tld = *(const ulonglong2*)(wp + sn * DVv + q * 4);
            wn[2*q] = tld.x; wn[2*q+1] = tld.y;
        }
        float en = ep[sn * DKk], an = ap[sn * DKk];

        u64 ne2 = pk2(-ec, -ec);
        u64 a2  = pk2(ac, ac);
        u64 rA = 0, rB = 0, rC = 0, rD = 0;
#pragma unroll
        for (int p = 0; p < 8; p += 4) {
            rA = fma2(wc[p],   M[p],   rA);
            M[p]   = fma2(wc[p],   fma2(M[p],   ne2, a2), M[p]);
            rB = fma2(wc[p+1], M[p+1], rB);
            M[p+1] = fma2(wc[p+1], fma2(M[p+1], ne2, a2), M[p+1]);
            rC = fma2(wc[p+2], M[p+2], rC);
            M[p+2] = fma2(wc[p+2], fma2(M[p+2], ne2, a2), M[p+2]);
            rD = fma2(wc[p+3], M[p+3], rD);
            M[p+3] = fma2(wc[p+3], fma2(M[p+3], ne2, a2), M[p+3]);
        }
        float2 fr = up2(add2(add2(rA, rB), add2(rC, rD)));
        float part = fr.x + fr.y;
        part += __shfl_xor_sync(0xffffffffu, part, 8);
        part += __shfl_xor_sync(0xffffffffu, part, 16);
        if (vs == 0) rp[s * DKk] = part;

#pragma unroll
        for (int p = 0; p < 8; p++) wc[p] = wn[p];
        ec = en; ac = an;
    }
}

// ---------------------------------------------------------------------------
// Kernel 4: pred, K-half split warps, SOFTWARE-PIPELINED inner loop.
// ---------------------------------------------------------------------------
__global__ __launch_bounds__(512, 1)
void kern_pred(const int* __restrict__ qseq,
               const float* __restrict__ k_emb,
               const float* __restrict__ fW, const float* __restrict__ fb,
               const float* __restrict__ pW, const float* __restrict__ pb,
               float* __restrict__ out) {
    extern __shared__ float sm[];
    float* shAT = sm;                    // [256 kk][68]
    float* shB  = sm + 256 * 68;         // [256][128]
    float* shfb = shB + 256 * 128;       // [128]
    float* shpW = shfb + 128;            // [128]
    __shared__ int shq[64];

    const int tid = threadIdx.x;
    const int lane = tid & 31;
    const int wid  = tid >> 5;

#pragma unroll
    for (int i = 0; i < 16; i++) {
        int idx = tid + i * 512;
        *(float4*)(shB + idx * 4) = *(const float4*)(fW + idx * 4);
    }
    if (tid < 128) { shfb[tid] = fb[tid]; shpW[tid] = pW[tid]; }
    const float pbv = pb[0];

    const int khalf = wid >> 3;
    const int rowb  = (wid & 7) * 8;
    const int c0    = lane * 4;
    const int kbase = khalf * 128;

    for (int t = blockIdx.x; t < ROWS / 64; t += gridDim.x) {
        __syncthreads();   // protects shq + reduction buffer from prev tile
        if (tid < 64) shq[tid] = qseq[t * 64 + tid];
        __syncthreads();
#pragma unroll
        for (int i = 0; i < 8; i++) {
            int idx = tid + i * 512;        // 0..4095 = 64 rows x 64 kc4
            int r = idx & 63, kc4 = idx >> 6;
            float4 v;
            if (kc4 < 32)
                v = *(const float4*)(g_reads + (size_t)(t * 64 + r) * DKk + kc4 * 4);
            else
                v = *(const float4*)(k_emb + (size_t)shq[r] * DKk + (kc4 - 32) * 4);
            shAT[(kc4 * 4 + 0) * 68 + r] = v.x;
            shAT[(kc4 * 4 + 1) * 68 + r] = v.y;
            shAT[(kc4 * 4 + 2) * 68 + r] = v.z;
            shAT[(kc4 * 4 + 3) * 68 + r] = v.w;
        }
        __syncthreads();

        // pipelined mainloop over this warp's K-half
        const float* abp0 = shAT + kbase * 68 + rowb;
        ulonglong2 cA = *(const ulonglong2*)(abp0);
        ulonglong2 cB = *(const ulonglong2*)(abp0 + 4);
        float4 cbf = *(const float4*)(shB + (kbase << 7) + c0);
        u64 acc[4][4] = {};
#pragma unroll 4
        for (int kk = 0; kk < 128; kk++) {
            int kn = kbase + ((kk + 1 < 128) ? kk + 1 : 0);
            const float* abn = shAT + kn * 68 + rowb;
            ulonglong2 nA = *(const ulonglong2*)(abn);
            ulonglong2 nB = *(const ulonglong2*)(abn + 4);
            float4 nbf = *(const float4*)(shB + (kn << 7) + c0);
            u64 b0 = pk2(cbf.x, cbf.x), b1 = pk2(cbf.y, cbf.y);
            u64 b2 = pk2(cbf.z, cbf.z), b3 = pk2(cbf.w, cbf.w);
            acc[0][0] = fma2(cA.x, b0, acc[0][0]);
            acc[0][1] = fma2(cA.x, b1, acc[0][1]);
            acc[0][2] = fma2(cA.x, b2, acc[0][2]);
            acc[0][3] = fma2(cA.x, b3, acc[0][3]);
            acc[1][0] = fma2(cA.y, b0, acc[1][0]);
            acc[1][1] = fma2(cA.y, b1, acc[1][1]);
            acc[1][2] = fma2(cA.y, b2, acc[1][2]);
            acc[1][3] = fma2(cA.y, b3, acc[1][3]);
            acc[2][0] = fma2(cB.x, b0, acc[2][0]);
            acc[2][1] = fma2(cB.x, b1, acc[2][1]);
            acc[2][2] = fma2(cB.x, b2, acc[2][2]);
            acc[2][3] = fma2(cB.x, b3, acc[2][3]);
            acc[3][0] = fma2(cB.y, b0, acc[3][0]);
            acc[3][1] = fma2(cB.y, b1, acc[3][1]);
            acc[3][2] = fma2(cB.y, b2, acc[3][2]);
            acc[3][3] = fma2(cB.y, b3, acc[3][3]);
            cA = nA; cB = nB; cbf = nbf;
        }

        // combine K-halves: warps 8-15 dump partials into smem (over shAT)
        __syncthreads();
        u64* shRed = (u64*)shAT;   // [8 rowg][32 lane][16]
        if (khalf == 1) {
            u64* dst = shRed + ((size_t)(wid & 7) * 32 + lane) * 16;
#pragma unroll
            for (int rp = 0; rp < 4; rp++)
#pragma unroll
                for (int c = 0; c < 4; c++) dst[rp * 4 + c] = acc[rp][c];
        }
        __syncthreads();
        if (khalf == 0) {
            const u64* src = shRed + ((size_t)(wid & 7) * 32 + lane) * 16;
#pragma unroll
            for (int rp = 0; rp < 4; rp++)
#pragma unroll
                for (int c = 0; c < 4; c++) acc[rp][c] = add2(acc[rp][c], src[rp * 4 + c]);

            float f0 = shfb[c0], f1 = shfb[c0+1], f2 = shfb[c0+2], f3 = shfb[c0+3];
            float p0 = shpW[c0], p1 = shpW[c0+1], p2 = shpW[c0+2], p3 = shpW[c0+3];
#pragma unroll
            for (int rp = 0; rp < 4; rp++) {
                float2 v0 = up2(acc[rp][0]), v1 = up2(acc[rp][1]);
                float2 v2 = up2(acc[rp][2]), v3 = up2(acc[rp][3]);
                float plo = tanha(v0.x + f0) * p0;
                plo = fmaf(tanha(v1.x + f1), p1, plo);
                plo = fmaf(tanha(v2.x + f2), p2, plo);
                plo = fmaf(tanha(v3.x + f3), p3, plo);
                float phi = tanha(v0.y + f0) * p0;
                phi = fmaf(tanha(v1.y + f1), p1, phi);
                phi = fmaf(tanha(v2.y + f2), p2, phi);
                phi = fmaf(tanha(v3.y + f3), p3, phi);
#pragma unroll
                for (int o = 1; o < 32; o <<= 1) {
                    plo += __shfl_xor_sync(0xffffffffu, plo, o);
                    phi += __shfl_xor_sync(0xffffffffu, phi, o);
                }
                if (lane == 0) {
                    int row = t * 64 + rowb + 2 * rp;
                    out[row]     = 1.0f / (1.0f + __expf(-(plo + pbv)));
                    out[row + 1] = 1.0f / (1.0f + __expf(-(phi + pbv)));
                }
            }
        }
    }
}

// ---------------------------------------------------------------------------
extern "C" void kernel_launch(void* const* d_in, const int* in_sizes, int n_in,
                              void* d_out, int out_size) {
    (void)in_sizes; (void)n_in; (void)out_size;
    const int*   qseq  = (const int*)d_in[0];
    const int*   cseq  = (const int*)d_in[1];
    const float* k_emb = (const float*)d_in[2];
    const float* v_emb = (const float*)d_in[3];
    const float* Mk    = (const float*)d_in[4];
    const float* Mv0   = (const float*)d_in[5];
    const float* fW    = (const float*)d_in[6];
    const float* fb    = (const float*)d_in[7];
    const float* eW    = (const float*)d_in[8];
    const float* eb    = (const float*)d_in[9];
    const float* aW    = (const float*)d_in[10];
    const float* ab    = (const float*)d_in[11];
    const float* pW    = (const float*)d_in[12];
    const float* pb    = (const float*)d_in[13];
    float* out = (float*)d_out;

    const int smw  = (128*264 + 128*68) * 4;                   // 169984
    const int smea = (128*68 + 2*128*128 + 256) * 4;           // 166912
    const int smp  = (256*68 + 256*128 + 256) * 4;             // 201728

    cudaFuncSetAttribute(kern_w,    cudaFuncAttributeMaxDynamicSharedMemorySize, smw);
    cudaFuncSetAttribute(kern_ea,   cudaFuncAttributeMaxDynamicSharedMemorySize, smea);
    cudaFuncSetAttribute(kern_pred, cudaFuncAttributeMaxDynamicSharedMemorySize, smp);

    kern_w   <<<100, 512, smw>>>(qseq, k_emb, Mk);
    kern_ea  <<<148, 512, smea>>>(qseq, cseq, v_emb, eW, eb, aW, ab);
    kern_scan<<<128, 512>>>(Mv0);
    kern_pred<<<148, 512, smp>>>(qseq, k_emb, fW, fb, pW, pb, out);
}

// round 17
// speedup vs baseline: 1.2731x; 1.2731x over previous
#include <cuda_runtime.h>
#include <cuda_bf16.h>
#include <cstdint>

#define NQ 10000
#define BB 128
#define SS 200
#define DKk 128
#define DVv 64
#define ROWS (BB*SS)     // 25600

typedef unsigned long long u64;

__device__ __forceinline__ u64 pk2(float lo, float hi) {
    u64 r; asm("mov.b64 %0,{%1,%2};" : "=l"(r) : "f"(lo), "f"(hi)); return r;
}
__device__ __forceinline__ float2 up2(u64 a) {
    float2 v; asm("mov.b64 {%0,%1},%2;" : "=f"(v.x), "=f"(v.y) : "l"(a)); return v;
}
__device__ __forceinline__ u64 fma2(u64 a, u64 b, u64 c) {
    u64 d; asm("fma.rn.f32x2 %0,%1,%2,%3;" : "=l"(d) : "l"(a), "l"(b), "l"(c)); return d;
}
__device__ __forceinline__ u64 add2(u64 a, u64 b) {
    u64 d; asm("add.rn.f32x2 %0,%1,%2;" : "=l"(d) : "l"(a), "l"(b)); return d;
}
__device__ __forceinline__ float tanha(float x) {
    float y; asm("tanh.approx.f32 %0,%1;" : "=f"(y) : "f"(x)); return y;
}

// Scratch
__device__ float g_w[ROWS*DVv];
__device__ float g_e[ROWS*DKk];
__device__ float g_a[ROWS*DKk];
__device__ float g_reads[ROWS*DKk];

// ---------------------------------------------------------------------------
// Kernel 1: w = softmax(k_emb[q] @ Mk^T). 256-row tiles, grid 100, 512 thr.
// ---------------------------------------------------------------------------
__global__ __launch_bounds__(512, 1)
void kern_w(const int* __restrict__ qseq,
            const float* __restrict__ k_emb,
            const float* __restrict__ Mk) {
    extern __shared__ float sm[];
    float* shAT = sm;               // [128][264]
    float* shBt = sm + 128 * 264;   // [128][68]
    __shared__ int shq[256];

    const int tid = threadIdx.x;
    const int lane = tid & 31;
    const int wid  = tid >> 5;

#pragma unroll
    for (int i = 0; i < 4; i++) {
        int idx = tid + i * 512;
        int col = idx & 63, kc4 = idx >> 6;
        float4 v = *(const float4*)(Mk + col * DKk + kc4 * 4);
        shBt[(kc4 * 4 + 0) * 68 + col] = v.x;
        shBt[(kc4 * 4 + 1) * 68 + col] = v.y;
        shBt[(kc4 * 4 + 2) * 68 + col] = v.z;
        shBt[(kc4 * 4 + 3) * 68 + col] = v.w;
    }

    const int rowb = wid * 16;
    const int c0   = lane * 2;

    for (int t = blockIdx.x; t < ROWS / 256; t += gridDim.x) {
        __syncthreads();
        if (tid < 256) shq[tid] = qseq[t * 256 + tid];
        __syncthreads();
#pragma unroll
        for (int i = 0; i < 16; i++) {
            int idx = tid + i * 512;
            int r = idx & 255, kc4 = idx >> 8;
            float4 v = *(const float4*)(k_emb + (size_t)shq[r] * DKk + kc4 * 4);
            shAT[(kc4 * 4 + 0) * 264 + r] = v.x;
            shAT[(kc4 * 4 + 1) * 264 + r] = v.y;
            shAT[(kc4 * 4 + 2) * 264 + r] = v.z;
            shAT[(kc4 * 4 + 3) * 264 + r] = v.w;
        }
        __syncthreads();

        u64 acc[8][2] = {};
#pragma unroll 4
        for (int kk = 0; kk < DKk; kk++) {
            const float* ab = shAT + kk * 264 + rowb;
            ulonglong2 a01 = *(const ulonglong2*)(ab);
            ulonglong2 a23 = *(const ulonglong2*)(ab + 4);
            ulonglong2 a45 = *(const ulonglong2*)(ab + 8);
            ulonglong2 a67 = *(const ulonglong2*)(ab + 12);
            float2 bf = *(const float2*)(shBt + kk * 68 + c0);
            u64 b0 = pk2(bf.x, bf.x), b1 = pk2(bf.y, bf.y);
            acc[0][0] = fma2(a01.x, b0, acc[0][0]);
            acc[0][1] = fma2(a01.x, b1, acc[0][1]);
            acc[1][0] = fma2(a01.y, b0, acc[1][0]);
            acc[1][1] = fma2(a01.y, b1, acc[1][1]);
            acc[2][0] = fma2(a23.x, b0, acc[2][0]);
            acc[2][1] = fma2(a23.x, b1, acc[2][1]);
            acc[3][0] = fma2(a23.y, b0, acc[3][0]);
            acc[3][1] = fma2(a23.y, b1, acc[3][1]);
            acc[4][0] = fma2(a45.x, b0, acc[4][0]);
            acc[4][1] = fma2(a45.x, b1, acc[4][1]);
            acc[5][0] = fma2(a45.y, b0, acc[5][0]);
            acc[5][1] = fma2(a45.y, b1, acc[5][1]);
            acc[6][0] = fma2(a67.x, b0, acc[6][0]);
            acc[6][1] = fma2(a67.x, b1, acc[6][1]);
            acc[7][0] = fma2(a67.y, b0, acc[7][0]);
            acc[7][1] = fma2(a67.y, b1, acc[7][1]);
        }
#pragma unroll
        for (int rp = 0; rp < 8; rp++) {
            float2 v0 = up2(acc[rp][0]), v1 = up2(acc[rp][1]);
            float mlo = fmaxf(v0.x, v1.x);
            float mhi = fmaxf(v0.y, v1.y);
#pragma unroll
            for (int o = 1; o < 32; o <<= 1) {
                mlo = fmaxf(mlo, __shfl_xor_sync(0xffffffffu, mlo, o));
                mhi = fmaxf(mhi, __shfl_xor_sync(0xffffffffu, mhi, o));
            }
            float l0 = __expf(v0.x - mlo), l1 = __expf(v1.x - mlo);
            float h0 = __expf(v0.y - mhi), h1 = __expf(v1.y - mhi);
            float slo = l0 + l1, shi = h0 + h1;
#pragma unroll
            for (int o = 1; o < 32; o <<= 1) {
                slo += __shfl_xor_sync(0xffffffffu, slo, o);
                shi += __shfl_xor_sync(0xffffffffu, shi, o);
            }
            float ilo = 1.0f / slo, ihi = 1.0f / shi;
            int row = t * 256 + rowb + 2 * rp;
            *(float2*)(g_w + (size_t)row * DVv + c0) = make_float2(l0 * ilo, l1 * ilo);
            *(float2*)(g_w + (size_t)(row + 1) * DVv + c0) = make_float2(h0 * ihi, h1 * ihi);
        }
    }
}

// ---------------------------------------------------------------------------
// Kernel 2: e = sigmoid(v@eW+eb), a = tanh(v@aW+ab). 64-row tiles, grid 148.
// Warps split by matrix; software-pipelined inner loop.
// ---------------------------------------------------------------------------
__global__ __launch_bounds__(512, 1)
void kern_ea(const int* __restrict__ qseq, const int* __restrict__ cseq,
             const float* __restrict__ v_emb,
             const float* __restrict__ eW, const float* __restrict__ eb,
             const float* __restrict__ aW, const float* __restrict__ ab) {
    extern __shared__ float sm[];
    float* shAT = sm;                    // [128][68]
    float* shE  = sm + 128 * 68;         // [128][128]
    float* shAw = shE + 128 * 128;       // [128][128]
    float* shEb = shAw + 128 * 128;      // [128]
    float* shAb = shEb + 128;            // [128]
    __shared__ int shx[64];

    const int tid = threadIdx.x;
    const int lane = tid & 31;
    const int wid  = tid >> 5;

#pragma unroll
    for (int i = 0; i < 8; i++) {
        int idx = tid + i * 512;
        *(float4*)(shE  + idx * 4) = *(const float4*)(eW + idx * 4);
        *(float4*)(shAw + idx * 4) = *(const float4*)(aW + idx * 4);
    }
    if (tid < 128) { shEb[tid] = eb[tid]; shAb[tid] = ab[tid]; }

    const int mat  = wid >> 3;
    const int rowb = (wid & 7) * 8;
    const int c0   = lane * 4;
    const float* W = mat ? shAw : shE;

    for (int t = blockIdx.x; t < ROWS / 64; t += gridDim.x) {
        __syncthreads();
        if (tid < 64) {
            int row = t * 64 + tid;
            shx[tid] = qseq[row] + NQ * cseq[row];
        }
        __syncthreads();
#pragma unroll
        for (int i = 0; i < 4; i++) {
            int idx = tid + i * 512;
            int r = idx & 63, kc4 = idx >> 6;
            float4 v = *(const float4*)(v_emb + (size_t)shx[r] * DKk + kc4 * 4);
            shAT[(kc4 * 4 + 0) * 68 + r] = v.x;
            shAT[(kc4 * 4 + 1) * 68 + r] = v.y;
            shAT[(kc4 * 4 + 2) * 68 + r] = v.z;
            shAT[(kc4 * 4 + 3) * 68 + r] = v.w;
        }
        __syncthreads();

        ulonglong2 cA = *(const ulonglong2*)(shAT + rowb);
        ulonglong2 cB = *(const ulonglong2*)(shAT + rowb + 4);
        float4 cbf = *(const float4*)(W + c0);
        u64 acc[4][4] = {};
#pragma unroll 4
        for (int kk = 0; kk < DKk; kk++) {
            int kn = (kk + 1 < DKk) ? kk + 1 : 0;
            const float* abn = shAT + kn * 68 + rowb;
            ulonglong2 nA = *(const ulonglong2*)(abn);
            ulonglong2 nB = *(const ulonglong2*)(abn + 4);
            float4 nbf = *(const float4*)(W + (kn << 7) + c0);
            u64 b0 = pk2(cbf.x, cbf.x), b1 = pk2(cbf.y, cbf.y);
            u64 b2 = pk2(cbf.z, cbf.z), b3 = pk2(cbf.w, cbf.w);
            acc[0][0] = fma2(cA.x, b0, acc[0][0]);
            acc[0][1] = fma2(cA.x, b1, acc[0][1]);
            acc[0][2] = fma2(cA.x, b2, acc[0][2]);
            acc[0][3] = fma2(cA.x, b3, acc[0][3]);
            acc[1][0] = fma2(cA.y, b0, acc[1][0]);
            acc[1][1] = fma2(cA.y, b1, acc[1][1]);
            acc[1][2] = fma2(cA.y, b2, acc[1][2]);
            acc[1][3] = fma2(cA.y, b3, acc[1][3]);
            acc[2][0] = fma2(cB.x, b0, acc[2][0]);
            acc[2][1] = fma2(cB.x, b1, acc[2][1]);
            acc[2][2] = fma2(cB.x, b2, acc[2][2]);
            acc[2][3] = fma2(cB.x, b3, acc[2][3]);
            acc[3][0] = fma2(cB.y, b0, acc[3][0]);
            acc[3][1] = fma2(cB.y, b1, acc[3][1]);
            acc[3][2] = fma2(cB.y, b2, acc[3][2]);
            acc[3][3] = fma2(cB.y, b3, acc[3][3]);
            cA = nA; cB = nB; cbf = nbf;
        }
        const float* bias = mat ? shAb : shEb;
        float b0 = bias[c0], b1 = bias[c0+1], b2 = bias[c0+2], b3 = bias[c0+3];
        float* outbuf = mat ? g_a : g_e;
#pragma unroll
        for (int rp = 0; rp < 4; rp++) {
            float2 v0 = up2(acc[rp][0]), v1 = up2(acc[rp][1]);
            float2 v2 = up2(acc[rp][2]), v3 = up2(acc[rp][3]);
            int row = t * 64 + rowb + 2 * rp;
            float4 olo, ohi;
            if (mat) {
                olo = make_float4(tanha(v0.x+b0), tanha(v1.x+b1), tanha(v2.x+b2), tanha(v3.x+b3));
                ohi = make_float4(tanha(v0.y+b0), tanha(v1.y+b1), tanha(v2.y+b2), tanha(v3.y+b3));
            } else {
                olo = make_float4(1.0f/(1.0f+__expf(-(v0.x+b0))), 1.0f/(1.0f+__expf(-(v1.x+b1))),
                                  1.0f/(1.0f+__expf(-(v2.x+b2))), 1.0f/(1.0f+__expf(-(v3.x+b3))));
                ohi = make_float4(1.0f/(1.0f+__expf(-(v0.y+b0))), 1.0f/(1.0f+__expf(-(v1.y+b1))),
                                  1.0f/(1.0f+__expf(-(v2.y+b2))), 1.0f/(1.0f+__expf(-(v3.y+b3))));
            }
            *(float4*)(outbuf + (size_t)row * DKk + c0) = olo;
            *(float4*)(outbuf + (size_t)(row + 1) * DKk + c0) = ohi;
        }
    }
}

// ---------------------------------------------------------------------------
// Kernel 3: sequential scan, barrier-free, 512 thr.
// ---------------------------------------------------------------------------
__global__ __launch_bounds__(512, 1)
void kern_scan(const float* __restrict__ Mv0) {
    const int b = blockIdx.x;
    const int tid = threadIdx.x;
    const int lane = tid & 31;
    const int wid  = tid >> 5;
    const int j  = wid * 8 + (lane & 7);
    const int vs = lane >> 3;
    const int vb = vs * 16;

    u64 M[8];
#pragma unroll
    for (int p = 0; p < 8; p++)
        M[p] = pk2(Mv0[(vb + 2*p) * DKk + j], Mv0[(vb + 2*p + 1) * DKk + j]);

    const float* wp = g_w + (size_t)b * SS * DVv + vb;
    const float* ep = g_e + (size_t)b * SS * DKk + j;
    const float* ap = g_a + (size_t)b * SS * DKk + j;
    float* rp = g_reads + (size_t)b * SS * DKk + j;

    u64 wc[8];
#pragma unroll
    for (int q = 0; q < 4; q++) {
        ulonglong2 tld = *(const ulonglong2*)(wp + q * 4);
        wc[2*q] = tld.x; wc[2*q+1] = tld.y;
    }
    float ec = ep[0], ac = ap[0];

#pragma unroll 2
    for (int s = 0; s < SS; s++) {
        int sn = (s + 1 < SS) ? s + 1 : s;
        u64 wn[8];
#pragma unroll
        for (int q = 0; q < 4; q++) {
            ulonglong2 tld = *(const ulonglong2*)(wp + sn * DVv + q * 4);
            wn[2*q] = tld.x; wn[2*q+1] = tld.y;
        }
        float en = ep[sn * DKk], an = ap[sn * DKk];

        u64 ne2 = pk2(-ec, -ec);
        u64 a2  = pk2(ac, ac);
        u64 rA = 0, rB = 0, rC = 0, rD = 0;
#pragma unroll
        for (int p = 0; p < 8; p += 4) {
            rA = fma2(wc[p],   M[p],   rA);
            M[p]   = fma2(wc[p],   fma2(M[p],   ne2, a2), M[p]);
            rB = fma2(wc[p+1], M[p+1], rB);
            M[p+1] = fma2(wc[p+1], fma2(M[p+1], ne2, a2), M[p+1]);
            rC = fma2(wc[p+2], M[p+2], rC);
            M[p+2] = fma2(wc[p+2], fma2(M[p+2], ne2, a2), M[p+2]);
            rD = fma2(wc[p+3], M[p+3], rD);
            M[p+3] = fma2(wc[p+3], fma2(M[p+3], ne2, a2), M[p+3]);
        }
        float2 fr = up2(add2(add2(rA, rB), add2(rC, rD)));
        float part = fr.x + fr.y;
        part += __shfl_xor_sync(0xffffffffu, part, 8);
        part += __shfl_xor_sync(0xffffffffu, part, 16);
        if (vs == 0) rp[s * DKk] = part;

#pragma unroll
        for (int p = 0; p < 8; p++) wc[p] = wn[p];
        ec = en; ac = an;
    }
}

// ---------------------------------------------------------------------------
// Kernel 4: pred via mma.sync m16n8k16 bf16 (baseline PTX, works on sm_103).
// 64-row tiles (400), grid 148 persistent, 512 thr.
// Warp w: rows (w&3)*16..+15, cols (w>>2)*32..+31 (4 n-blocks of 8).
// A [64][256] bf16 in smem, u32 stride 132; B = fW^T [128 n][256 k] bf16,
// u32 stride 132. Fragment LDS.32 loads are bank-conflict-free (bank=4*gr+tg).
// Epilogue: tanh+pW partial dot, quad shfl reduce, 4-warp smem reduce, sigmoid.
// ---------------------------------------------------------------------------
#define PR_RS 132   // u32 row stride

__device__ __forceinline__ void mma_bf16(float& d0, float& d1, float& d2, float& d3,
                                         uint32_t a0, uint32_t a1, uint32_t a2, uint32_t a3,
                                         uint32_t b0, uint32_t b1) {
    asm volatile("mma.sync.aligned.m16n8k16.row.col.f32.bf16.bf16.f32 "
                 "{%0,%1,%2,%3}, {%4,%5,%6,%7}, {%8,%9}, {%0,%1,%2,%3};"
                 : "+f"(d0), "+f"(d1), "+f"(d2), "+f"(d3)
                 : "r"(a0), "r"(a1), "r"(a2), "r"(a3), "r"(b0), "r"(b1));
}

__global__ __launch_bounds__(512, 1)
void kern_pred_mma(const int* __restrict__ qseq,
                   const float* __restrict__ k_emb,
                   const float* __restrict__ fW, const float* __restrict__ fb,
                   const float* __restrict__ pW, const float* __restrict__ pb,
                   float* __restrict__ out) {
    extern __shared__ uint32_t smu[];
    uint32_t* sA   = smu;                   // [64][132] u32 (bf16 pairs)
    uint32_t* sB   = smu + 64 * PR_RS;      // [128][132] u32
    float*   shfb  = (float*)(smu + 64 * PR_RS + 128 * PR_RS);  // [128]
    float*   shpW  = shfb + 128;            // [128]
    float*   red   = shpW + 128;            // [64][4]
    __shared__ int shq[64];

    const int tid  = threadIdx.x;
    const int lane = tid & 31;
    const int wid  = tid >> 5;
    const int gr   = lane >> 2;      // 0..7
    const int tg   = lane & 3;       // 0..3
    const int rw   = (wid & 3) * 16; // warp row base
    const int cbi  = wid >> 2;       // warp col-block index 0..3
    const int cb   = cbi * 32;       // warp col base

    // Stage B = fW^T bf16 once: u32 (n, k2) <- (fW[2k2][n], fW[2k2+1][n])
    for (int idx = tid; idx < 128 * 128; idx += 512) {
        int k2 = idx >> 7, n = idx & 127;   // consecutive lanes -> consecutive n
        float lo = fW[(2 * k2) * 128 + n];
        float hi = fW[(2 * k2 + 1) * 128 + n];
        __nv_bfloat162 p = __floats2bfloat162_rn(lo, hi);
        sB[n * PR_RS + k2] = *(uint32_t*)&p;
    }
    if (tid < 128) { shfb[tid] = fb[tid]; shpW[tid] = pW[tid]; }
    const float pbv = pb[0];
    __syncthreads();

    for (int t = blockIdx.x; t < ROWS / 64; t += gridDim.x) {
        __syncthreads();   // prior tile epilogue done before restaging
        if (tid < 64) shq[tid] = qseq[t * 64 + tid];
        __syncthreads();

        // Stage A bf16: 64 rows x 256 cols = 64 rows x 64 float4
#pragma unroll
        for (int i = 0; i < 8; i++) {
            int idx = tid + i * 512;           // 0..4095
            int r = idx & 63, f4 = idx >> 6;   // f4 = 0..63
            float4 v;
            if (f4 < 32)
                v = *(const float4*)(g_reads + (size_t)(t * 64 + r) * DKk + f4 * 4);
            else
                v = *(const float4*)(k_emb + (size_t)shq[r] * DKk + (f4 - 32) * 4);
            __nv_bfloat162 p0 = __floats2bfloat162_rn(v.x, v.y);
            __nv_bfloat162 p1 = __floats2bfloat162_rn(v.z, v.w);
            sA[r * PR_RS + f4 * 2]     = *(uint32_t*)&p0;
            sA[r * PR_RS + f4 * 2 + 1] = *(uint32_t*)&p1;
        }
        __syncthreads();

        float d[4][4] = {};
#pragma unroll
        for (int ks = 0; ks < 16; ks++) {
            const int kb = ks * 8;  // u32 offset for this k-step
            uint32_t a0 = sA[(rw + gr)     * PR_RS + kb + tg];
            uint32_t a1 = sA[(rw + gr + 8) * PR_RS + kb + tg];
            uint32_t a2 = sA[(rw + gr)     * PR_RS + kb + tg + 4];
            uint32_t a3 = sA[(rw + gr + 8) * PR_RS + kb + tg + 4];
#pragma unroll
            for (int nb = 0; nb < 4; nb++) {
                const int n = cb + nb * 8 + gr;
                uint32_t b0 = sB[n * PR_RS + kb + tg];
                uint32_t b1 = sB[n * PR_RS + kb + tg + 4];
                mma_bf16(d[nb][0], d[nb][1], d[nb][2], d[nb][3], a0, a1, a2, a3, b0, b1);
            }
        }

        // Epilogue: partial dot over this warp's 32 cols for rows rw+gr, rw+gr+8
        float pA = 0.0f, pB = 0.0f;
#pragma unroll
        for (int nb = 0; nb < 4; nb++) {
            int c0 = cb + nb * 8 + tg * 2;
            float f0 = shfb[c0], f1 = shfb[c0 + 1];
            float w0 = shpW[c0], w1 = shpW[c0 + 1];
            pA = fmaf(tanha(d[nb][0] + f0), w0, pA);
            pA = fmaf(tanha(d[nb][1] + f1), w1, pA);
            pB = fmaf(tanha(d[nb][2] + f0), w0, pB);
            pB = fmaf(tanha(d[nb][3] + f1), w1, pB);
        }
        pA += __shfl_xor_sync(0xffffffffu, pA, 1);
        pA += __shfl_xor_sync(0xffffffffu, pA, 2);
        pB += __shfl_xor_sync(0xffffffffu, pB, 1);
        pB += __shfl_xor_sync(0xffffffffu, pB, 2);
        if (tg == 0) {
            red[(rw + gr) * 4 + cbi]     = pA;
            red[(rw + gr + 8) * 4 + cbi] = pB;
        }
        __syncthreads();
        if (tid < 64) {
            float s = red[tid * 4] + red[tid * 4 + 1] + red[tid * 4 + 2] + red[tid * 4 + 3];
            out[t * 64 + tid] = 1.0f / (1.0f + __expf(-(s + pbv)));
        }
    }
}

// ---------------------------------------------------------------------------
extern "C" void kernel_launch(void* const* d_in, const int* in_sizes, int n_in,
                              void* d_out, int out_size) {
    (void)in_sizes; (void)n_in; (void)out_size;
    const int*   qseq  = (const int*)d_in[0];
    const int*   cseq  = (const int*)d_in[1];
    const float* k_emb = (const float*)d_in[2];
    const float* v_emb = (const float*)d_in[3];
    const float* Mk    = (const float*)d_in[4];
    const float* Mv0   = (const float*)d_in[5];
    const float* fW    = (const float*)d_in[6];
    const float* fb    = (const float*)d_in[7];
    const float* eW    = (const float*)d_in[8];
    const float* eb    = (const float*)d_in[9];
    const float* aW    = (const float*)d_in[10];
    const float* ab    = (const float*)d_in[11];
    const float* pW    = (const float*)d_in[12];
    const float* pb    = (const float*)d_in[13];
    float* out = (float*)d_out;

    const int smw  = (128*264 + 128*68) * 4;
    const int smea = (128*68 + 2*128*128 + 256) * 4;
    const int smp  = (64*PR_RS + 128*PR_RS + 128 + 128 + 64*4) * 4;  // ~103.5KB

    cudaFuncSetAttribute(kern_w,        cudaFuncAttributeMaxDynamicSharedMemorySize, smw);
    cudaFuncSetAttribute(kern_ea,       cudaFuncAttributeMaxDynamicSharedMemorySize, smea);
    cudaFuncSetAttribute(kern_pred_mma, cudaFuncAttributeMaxDynamicSharedMemorySize, smp);

    kern_w   <<<100, 512, smw>>>(qseq, k_emb, Mk);
    kern_ea  <<<148, 512, smea>>>(qseq, cseq, v_emb, eW, eb, aW, ab);
    kern_scan<<<128, 512>>>(Mv0);
    kern_pred_mma<<<148, 512, smp>>>(qseq, k_emb, fW, fb, pW, pb, out);
}